// round 5
// baseline (speedup 1.0000x reference)
#include <cuda_runtime.h>
#include <cuda_bf16.h>
#include <math.h>
#include <stdint.h>

#define DMODEL 768
#define VOCAB  8192
#define HIDDEN 3072
#define NBLOCKS 4
#define NTOK   4096
#define NHEAD  12
#define DHEAD  64

typedef __nv_bfloat16 bf16;

// -------- scratch (static __device__ — no allocation allowed) --------
__device__ float g_X [NTOK * DMODEL];
__device__ float g_O [NTOK * DMODEL];
__device__ float g_batt[NBLOCKS * DMODEL];

__device__ bf16 g_Xhi [NTOK * DMODEL],  g_Xlo [NTOK * DMODEL];
__device__ bf16 g_Hhi [NTOK * HIDDEN],  g_Hlo [NTOK * HIDDEN];
__device__ bf16 g_Ihi [NTOK * VOCAB],   g_Ilo [NTOK * VOCAB];      // Xin split
__device__ bf16 g_Ehi [VOCAB * DMODEL], g_Elo [VOCAB * DMODEL];    // emb_w
__device__ bf16 g_Vrhi[NBLOCKS * DMODEL * DMODEL], g_Vrlo[NBLOCKS * DMODEL * DMODEL];
__device__ bf16 g_Wohi[NBLOCKS * DMODEL * DMODEL], g_Wolo[NBLOCKS * DMODEL * DMODEL];
__device__ bf16 g_Athi[NBLOCKS * DMODEL * DMODEL], g_Atlo[NBLOCKS * DMODEL * DMODEL]; // Watt
__device__ bf16 g_W1hi[NBLOCKS * DMODEL * HIDDEN], g_W1lo[NBLOCKS * DMODEL * HIDDEN];
__device__ bf16 g_W2hi[NBLOCKS * HIDDEN * DMODEL], g_W2lo[NBLOCKS * HIDDEN * DMODEL];
__device__ bf16 g_Whhi[DMODEL * VOCAB], g_Whlo[DMODEL * VOCAB];    // Wout

// ======================= helpers =======================
__device__ __forceinline__ uint32_t pk_bf2(float f0, float f1) {
    uint32_t u;
    asm("cvt.rn.bf16x2.f32 %0, %1, %2;" : "=r"(u) : "f"(f1), "f"(f0));
    return u;
}
// split (a,b) -> packed hi bf16x2 + packed lo bf16x2
__device__ __forceinline__ void split2(float a, float b, uint32_t& hi, uint32_t& lo) {
    hi = pk_bf2(a, b);
    float ra = a - __uint_as_float(hi << 16);
    float rb = b - __uint_as_float(hi & 0xffff0000u);
    lo = pk_bf2(ra, rb);
}

__device__ __forceinline__ void ldsm_x4(uint32_t* r, const void* p) {
    uint32_t a = (uint32_t)__cvta_generic_to_shared(p);
    asm volatile("ldmatrix.sync.aligned.m8n8.x4.shared.b16 {%0,%1,%2,%3}, [%4];"
                 : "=r"(r[0]), "=r"(r[1]), "=r"(r[2]), "=r"(r[3]) : "r"(a));
}
__device__ __forceinline__ void ldsm_x4_t(uint32_t* r, const void* p) {
    uint32_t a = (uint32_t)__cvta_generic_to_shared(p);
    asm volatile("ldmatrix.sync.aligned.m8n8.x4.trans.shared.b16 {%0,%1,%2,%3}, [%4];"
                 : "=r"(r[0]), "=r"(r[1]), "=r"(r[2]), "=r"(r[3]) : "r"(a));
}
__device__ __forceinline__ void mma_bf16(float* c, const uint32_t* a, const uint32_t* b) {
    asm volatile("mma.sync.aligned.m16n8k16.row.col.f32.bf16.bf16.f32 "
                 "{%0,%1,%2,%3}, {%4,%5,%6,%7}, {%8,%9}, {%0,%1,%2,%3};"
                 : "+f"(c[0]), "+f"(c[1]), "+f"(c[2]), "+f"(c[3])
                 : "r"(a[0]), "r"(a[1]), "r"(a[2]), "r"(a[3]),
                   "r"(b[0]), "r"(b[1]));
}
__device__ __forceinline__ void cp16(void* smem, const void* gmem) {
    uint32_t s = (uint32_t)__cvta_generic_to_shared(smem);
    asm volatile("cp.async.cg.shared.global [%0], [%1], 16;" :: "r"(s), "l"(gmem));
}
__device__ __forceinline__ void cp_commit() { asm volatile("cp.async.commit_group;"); }
template<int W> __device__ __forceinline__ void cp_wait() {
    asm volatile("cp.async.wait_group %0;" :: "n"(W));
}

// ======================= pure-bf16 pipelined GEMM =======================
// C = Ahi@Bhi + Alo@Bhi + Ahi@Blo  (3 K-segments), 128x128x32 tiles, 8 warps,
// warp tile 32x64, 4-stage cp.async. M,N mult of 128; K mult of 32.
#define NS   4
#define ASTR 40    // 32 + 8 pad (bf16) -> 80B rows: LDSM + STS conflict-free
#define BSTR 136   // 128 + 8 pad      -> 272B rows: conflict-free
#define SMEM_BYTES ((NS*128*ASTR + NS*32*BSTR) * 2)

// OMODE bit0: write float C; bit1: write hi/lo split C
template<int RELU, int BATCHED, int OMODE>
__global__ void __launch_bounds__(256, 2) gemm_s(
    const bf16* __restrict__ Ahi, const bf16* __restrict__ Alo,
    const bf16* __restrict__ Bhi, const bf16* __restrict__ Blo,
    const float* __restrict__ bias,
    float* __restrict__ Cf, bf16* __restrict__ Chi, bf16* __restrict__ Clo,
    int M, int N, int K)
{
    extern __shared__ bf16 smem[];
    bf16* sA = smem;                    // [NS][128][ASTR]
    bf16* sB = smem + NS * 128 * ASTR;  // [NS][32][BSTR]

    if (BATCHED) {
        size_t z = blockIdx.z;
        Ahi += z * (size_t)M * K;  Alo += z * (size_t)M * K;
        Bhi += z * (size_t)K * N;  Blo += z * (size_t)K * N;
        if (OMODE & 1) Cf  += z * (size_t)M * N;
        if (OMODE & 2) { Chi += z * (size_t)M * N; Clo += z * (size_t)M * N; }
    }

    const int tid  = threadIdx.x;
    const int lane = tid & 31;
    const int wid  = tid >> 5;
    const int wm   = wid & 3;
    const int wn   = wid >> 2;
    const int bx   = blockIdx.x, by = blockIdx.y;

    const int KT = K / 32;          // tiles per segment
    const int NT = 3 * KT;

    auto load_tile = [&](int buf, int tt) {
        int seg = tt / KT;
        int kt  = (tt - seg * KT) * 32;
        const bf16* Ap = (seg == 1) ? Alo : Ahi;
        const bf16* Bp = (seg == 2) ? Blo : Bhi;
        const bf16* Ag = Ap + (size_t)(by * 128) * K + kt;
        const bf16* Bg = Bp + (size_t)kt * N + bx * 128;
        #pragma unroll
        for (int i = 0; i < 2; i++) {
            int l = tid + i * 256;
            int row = l >> 2, c = l & 3;
            cp16(sA + ((size_t)(buf * 128 + row) * ASTR + c * 8),
                 Ag + (size_t)row * K + c * 8);
        }
        #pragma unroll
        for (int i = 0; i < 2; i++) {
            int l = tid + i * 256;
            int row = l >> 4, c = l & 15;
            cp16(sB + ((size_t)(buf * 32 + row) * BSTR + c * 8),
                 Bg + (size_t)row * N + c * 8);
        }
        cp_commit();
    };

    float acc[2][8][4];
    #pragma unroll
    for (int i = 0; i < 2; i++)
        #pragma unroll
        for (int j = 0; j < 8; j++)
            #pragma unroll
            for (int k = 0; k < 4; k++) acc[i][j][k] = 0.f;

    const int fr  = lane & 15;
    const int fc8 = (lane >> 4) * 8;

    #pragma unroll
    for (int s = 0; s < NS - 1; s++) load_tile(s, s);

    for (int t = 0; t < NT; t++) {
        int tt = t + NS - 1;
        if (tt < NT) load_tile(tt % NS, tt);
        else        cp_commit();            // keep group count uniform
        cp_wait<NS - 1>();
        __syncthreads();

        const int buf = t % NS;
        uint32_t Af[2][2][4];               // [kk][mt]
        #pragma unroll
        for (int kk = 0; kk < 2; kk++)
            #pragma unroll
            for (int mt = 0; mt < 2; mt++)
                ldsm_x4(Af[kk][mt],
                        sA + ((size_t)(buf * 128 + wm * 32 + mt * 16 + fr) * ASTR
                              + kk * 16 + fc8));
        #pragma unroll
        for (int kk = 0; kk < 2; kk++) {
            #pragma unroll
            for (int g = 0; g < 4; g++) {
                uint32_t Bf[4];
                ldsm_x4_t(Bf, sB + ((size_t)(buf * 32 + kk * 16 + fr) * BSTR
                                    + wn * 64 + g * 16 + fc8));
                #pragma unroll
                for (int mt = 0; mt < 2; mt++) {
                    mma_bf16(acc[mt][g * 2 + 0], Af[kk][mt], Bf + 0);
                    mma_bf16(acc[mt][g * 2 + 1], Af[kk][mt], Bf + 2);
                }
            }
        }
        __syncthreads();
    }

    // epilogue
    const int rowC = by * 128 + wm * 32 + (lane >> 2);
    const int colC = bx * 128 + wn * 64 + (lane & 3) * 2;
    float bv[8][2];
    #pragma unroll
    for (int nt = 0; nt < 8; nt++) {
        bv[nt][0] = bias ? bias[colC + nt * 8]     : 0.f;
        bv[nt][1] = bias ? bias[colC + nt * 8 + 1] : 0.f;
    }
    #pragma unroll
    for (int mt = 0; mt < 2; mt++) {
        int r0 = rowC + mt * 16;
        #pragma unroll
        for (int nt = 0; nt < 8; nt++) {
            int c = colC + nt * 8;
            float v00 = acc[mt][nt][0] + bv[nt][0];
            float v01 = acc[mt][nt][1] + bv[nt][1];
            float v10 = acc[mt][nt][2] + bv[nt][0];
            float v11 = acc[mt][nt][3] + bv[nt][1];
            if (RELU) {
                v00 = fmaxf(v00, 0.f); v01 = fmaxf(v01, 0.f);
                v10 = fmaxf(v10, 0.f); v11 = fmaxf(v11, 0.f);
            }
            size_t o0 = (size_t)r0 * N + c, o1 = (size_t)(r0 + 8) * N + c;
            if (OMODE & 1) {
                *reinterpret_cast<float2*>(Cf + o0) = make_float2(v00, v01);
                *reinterpret_cast<float2*>(Cf + o1) = make_float2(v10, v11);
            }
            if (OMODE & 2) {
                uint32_t h, l;
                split2(v00, v01, h, l);
                *reinterpret_cast<uint32_t*>(Chi + o0) = h;
                *reinterpret_cast<uint32_t*>(Clo + o0) = l;
                split2(v10, v11, h, l);
                *reinterpret_cast<uint32_t*>(Chi + o1) = h;
                *reinterpret_cast<uint32_t*>(Clo + o1) = l;
            }
        }
    }
}

// ======================= split: float -> hi/lo bf16 =======================
__global__ void __launch_bounds__(256) split_f32(
    const float* __restrict__ src, bf16* __restrict__ hi, bf16* __restrict__ lo, int n2)
{
    int idx = blockIdx.x * blockDim.x + threadIdx.x;
    if (idx >= n2) return;
    float2 v = reinterpret_cast<const float2*>(src)[idx];
    uint32_t h, l;
    split2(v.x, v.y, h, l);
    reinterpret_cast<uint32_t*>(hi)[idx] = h;
    reinterpret_cast<uint32_t*>(lo)[idx] = l;
}

// Wv (NB,H,D,DK) -> Wvr[i][d][h*DK+e], split to hi/lo
__global__ void prep_wv_split(const float* __restrict__ Wv,
                              bf16* __restrict__ hi, bf16* __restrict__ lo) {
    int idx = blockIdx.x * blockDim.x + threadIdx.x;
    if (idx >= NBLOCKS * DMODEL * DMODEL) return;
    int i   = idx / (DMODEL * DMODEL);
    int rem = idx % (DMODEL * DMODEL);
    int d   = rem / DMODEL;
    int c   = rem % DMODEL;
    int h = c / DHEAD, e = c % DHEAD;
    float f = Wv[(((size_t)i * NHEAD + h) * DMODEL + d) * DHEAD + e];
    bf16 fh = __float2bfloat16_rn(f);
    hi[idx] = fh;
    lo[idx] = __float2bfloat16_rn(f - __bfloat162float(fh));
}

__global__ void prep_batt(const float* __restrict__ bv, const float* __restrict__ Wo,
                          const float* __restrict__ bo, float* __restrict__ batt) {
    int i = blockIdx.y;
    int j = blockIdx.x * blockDim.x + threadIdx.x;
    if (j >= DMODEL) return;
    const float* w = Wo + (size_t)i * DMODEL * DMODEL;
    const float* b = bv + (size_t)i * DMODEL;
    float s = bo[(size_t)i * DMODEL + j];
    for (int c = 0; c < DMODEL; c++) s += b[c] * w[(size_t)c * DMODEL + j];
    batt[(size_t)i * DMODEL + j] = s;
}

// ======================= add + layernorm (+ split output) =======================
__device__ __forceinline__ float block_reduce_sum(float v, float* sh) {
    #pragma unroll
    for (int o = 16; o > 0; o >>= 1) v += __shfl_xor_sync(0xffffffffu, v, o);
    __syncthreads();
    if ((threadIdx.x & 31) == 0) sh[threadIdx.x >> 5] = v;
    __syncthreads();
    float t = (threadIdx.x < 8) ? sh[threadIdx.x] : 0.f;
    if (threadIdx.x < 32) {
        #pragma unroll
        for (int o = 4; o > 0; o >>= 1) t += __shfl_xor_sync(0xffffffffu, t, o);
        if (threadIdx.x == 0) sh[0] = t;
    }
    __syncthreads();
    return sh[0];
}

__global__ void __launch_bounds__(256) add_ln_split(
    float* __restrict__ X, const float* __restrict__ O,
    bf16* __restrict__ Xhi, bf16* __restrict__ Xlo)
{
    __shared__ float sh[8];
    const size_t base = (size_t)blockIdx.x * DMODEL;
    float v[3];
    float s = 0.f;
    #pragma unroll
    for (int j = 0; j < 3; j++) {
        int c = threadIdx.x + j * 256;
        float t = X[base + c] + O[base + c];
        v[j] = t; s += t;
    }
    float mu = block_reduce_sum(s, sh) * (1.f / DMODEL);
    float q = 0.f;
    #pragma unroll
    for (int j = 0; j < 3; j++) { float d = v[j] - mu; q += d * d; }
    float var = block_reduce_sum(q, sh) * (1.f / DMODEL);
    float inv = rsqrtf(var);
    #pragma unroll
    for (int j = 0; j < 3; j++) {
        int c = threadIdx.x + j * 256;
        float xn = (v[j] - mu) * inv;
        X[base + c] = xn;
        bf16 h = __float2bfloat16_rn(xn);
        Xhi[base + c] = h;
        Xlo[base + c] = __float2bfloat16_rn(xn - __bfloat162float(h));
    }
}

// ======================= row softmax over VOCAB =======================
__global__ void __launch_bounds__(256) softmax_rows(float* __restrict__ X) {
    __shared__ float sh[8];
    const size_t base = (size_t)blockIdx.x * VOCAB;
    float v[32];
    float m = -INFINITY;
    #pragma unroll
    for (int j = 0; j < 32; j++) {
        v[j] = X[base + threadIdx.x + j * 256];
        m = fmaxf(m, v[j]);
    }
    #pragma unroll
    for (int o = 16; o > 0; o >>= 1) m = fmaxf(m, __shfl_xor_sync(0xffffffffu, m, o));
    if ((threadIdx.x & 31) == 0) sh[threadIdx.x >> 5] = m;
    __syncthreads();
    float mm = (threadIdx.x < 8) ? sh[threadIdx.x] : -INFINITY;
    if (threadIdx.x < 32) {
        #pragma unroll
        for (int o = 4; o > 0; o >>= 1) mm = fmaxf(mm, __shfl_xor_sync(0xffffffffu, mm, o));
        if (threadIdx.x == 0) sh[0] = mm;
    }
    __syncthreads();
    m = sh[0];
    __syncthreads();

    float s = 0.f;
    #pragma unroll
    for (int j = 0; j < 32; j++) { v[j] = expf(v[j] - m); s += v[j]; }
    float tot = block_reduce_sum(s, sh);
    float inv = 1.f / tot;
    #pragma unroll
    for (int j = 0; j < 32; j++) X[base + threadIdx.x + j * 256] = v[j] * inv;
}

// ======================= launch =======================
extern "C" void kernel_launch(void* const* d_in, const int* in_sizes, int n_in,
                              void* d_out, int out_size) {
    const float* Xin   = (const float*)d_in[0];
    const float* emb_w = (const float*)d_in[1];
    const float* emb_b = (const float*)d_in[2];
    // d_in[3..6] = Wq,bq,Wk,bk — mathematically unused (softmax row-sum == 1)
    const float* Wv    = (const float*)d_in[7];
    const float* bv    = (const float*)d_in[8];
    const float* Wo    = (const float*)d_in[9];
    const float* bo    = (const float*)d_in[10];
    const float* W1    = (const float*)d_in[11];
    const float* b1    = (const float*)d_in[12];
    const float* W2    = (const float*)d_in[13];
    const float* b2    = (const float*)d_in[14];
    const float* Wout  = (const float*)d_in[15];
    const float* bout  = (const float*)d_in[16];
    float* out = (float*)d_out;

    float *pX, *pO, *pBatt;
    bf16 *pXhi, *pXlo, *pHhi, *pHlo, *pIhi, *pIlo, *pEhi, *pElo;
    bf16 *pVrhi, *pVrlo, *pWohi, *pWolo, *pAthi, *pAtlo;
    bf16 *pW1hi, *pW1lo, *pW2hi, *pW2lo, *pWhhi, *pWhlo;
    cudaGetSymbolAddress((void**)&pX,    g_X);
    cudaGetSymbolAddress((void**)&pO,    g_O);
    cudaGetSymbolAddress((void**)&pBatt, g_batt);
    cudaGetSymbolAddress((void**)&pXhi,  g_Xhi);  cudaGetSymbolAddress((void**)&pXlo, g_Xlo);
    cudaGetSymbolAddress((void**)&pHhi,  g_Hhi);  cudaGetSymbolAddress((void**)&pHlo, g_Hlo);
    cudaGetSymbolAddress((void**)&pIhi,  g_Ihi);  cudaGetSymbolAddress((void**)&pIlo, g_Ilo);
    cudaGetSymbolAddress((void**)&pEhi,  g_Ehi);  cudaGetSymbolAddress((void**)&pElo, g_Elo);
    cudaGetSymbolAddress((void**)&pVrhi, g_Vrhi); cudaGetSymbolAddress((void**)&pVrlo, g_Vrlo);
    cudaGetSymbolAddress((void**)&pWohi, g_Wohi); cudaGetSymbolAddress((void**)&pWolo, g_Wolo);
    cudaGetSymbolAddress((void**)&pAthi, g_Athi); cudaGetSymbolAddress((void**)&pAtlo, g_Atlo);
    cudaGetSymbolAddress((void**)&pW1hi, g_W1hi); cudaGetSymbolAddress((void**)&pW1lo, g_W1lo);
    cudaGetSymbolAddress((void**)&pW2hi, g_W2hi); cudaGetSymbolAddress((void**)&pW2lo, g_W2lo);
    cudaGetSymbolAddress((void**)&pWhhi, g_Whhi); cudaGetSymbolAddress((void**)&pWhlo, g_Whlo);

    // raise dynamic smem limit for all GEMM instantiations (idempotent)
    cudaFuncSetAttribute(gemm_s<0,1,2>, cudaFuncAttributeMaxDynamicSharedMemorySize, SMEM_BYTES);
    cudaFuncSetAttribute(gemm_s<0,0,3>, cudaFuncAttributeMaxDynamicSharedMemorySize, SMEM_BYTES);
    cudaFuncSetAttribute(gemm_s<0,0,1>, cudaFuncAttributeMaxDynamicSharedMemorySize, SMEM_BYTES);
    cudaFuncSetAttribute(gemm_s<1,0,2>, cudaFuncAttributeMaxDynamicSharedMemorySize, SMEM_BYTES);

    // ---- one-time splits ----
    auto nb2 = [](long n) { return (int)((n / 2 + 255) / 256); };
    split_f32<<<nb2((long)NTOK * VOCAB), 256>>>(Xin, pIhi, pIlo, NTOK * VOCAB / 2);
    split_f32<<<nb2((long)VOCAB * DMODEL), 256>>>(emb_w, pEhi, pElo, VOCAB * DMODEL / 2);
    split_f32<<<nb2((long)NBLOCKS * DMODEL * DMODEL), 256>>>(Wo, pWohi, pWolo, NBLOCKS * DMODEL * DMODEL / 2);
    split_f32<<<nb2((long)NBLOCKS * DMODEL * HIDDEN), 256>>>(W1, pW1hi, pW1lo, NBLOCKS * DMODEL * HIDDEN / 2);
    split_f32<<<nb2((long)NBLOCKS * HIDDEN * DMODEL), 256>>>(W2, pW2hi, pW2lo, NBLOCKS * HIDDEN * DMODEL / 2);
    split_f32<<<nb2((long)DMODEL * VOCAB), 256>>>(Wout, pWhhi, pWhlo, DMODEL * VOCAB / 2);
    prep_wv_split<<<(NBLOCKS * DMODEL * DMODEL + 255) / 256, 256>>>(Wv, pVrhi, pVrlo);
    prep_batt<<<dim3(DMODEL / 256, NBLOCKS), 256>>>(bv, Wo, bo, pBatt);

    // ---- Watt[i] = Wvr[i] @ Wo[i] (batched), written directly as hi/lo ----
    gemm_s<0,1,2><<<dim3(DMODEL / 128, DMODEL / 128, NBLOCKS), 256, SMEM_BYTES>>>(
        pVrhi, pVrlo, pWohi, pWolo, nullptr,
        nullptr, pAthi, pAtlo, DMODEL, DMODEL, DMODEL);

    // ---- embedding: X = Xin @ emb_w + emb_b (float + split) ----
    gemm_s<0,0,3><<<dim3(DMODEL / 128, NTOK / 128), 256, SMEM_BYTES>>>(
        pIhi, pIlo, pEhi, pElo, emb_b,
        pX, pXhi, pXlo, NTOK, DMODEL, VOCAB);

    // ---- 4 transformer blocks (attention == fused V->O projection) ----
    for (int i = 0; i < NBLOCKS; i++) {
        size_t wo = (size_t)i * DMODEL * DMODEL;
        gemm_s<0,0,1><<<dim3(DMODEL / 128, NTOK / 128), 256, SMEM_BYTES>>>(
            pXhi, pXlo, pAthi + wo, pAtlo + wo, pBatt + (size_t)i * DMODEL,
            pO, nullptr, nullptr, NTOK, DMODEL, DMODEL);
        add_ln_split<<<NTOK, 256>>>(pX, pO, pXhi, pXlo);

        size_t w1 = (size_t)i * DMODEL * HIDDEN;
        gemm_s<1,0,2><<<dim3(HIDDEN / 128, NTOK / 128), 256, SMEM_BYTES>>>(
            pXhi, pXlo, pW1hi + w1, pW1lo + w1, b1 + (size_t)i * HIDDEN,
            nullptr, pHhi, pHlo, NTOK, HIDDEN, DMODEL);
        size_t w2 = (size_t)i * HIDDEN * DMODEL;
        gemm_s<0,0,1><<<dim3(DMODEL / 128, NTOK / 128), 256, SMEM_BYTES>>>(
            pHhi, pHlo, pW2hi + w2, pW2lo + w2, b2 + (size_t)i * DMODEL,
            pO, nullptr, nullptr, NTOK, DMODEL, HIDDEN);
        add_ln_split<<<NTOK, 256>>>(pX, pO, pXhi, pXlo);
    }

    // ---- output head + softmax (in-place on d_out) ----
    gemm_s<0,0,1><<<dim3(VOCAB / 128, NTOK / 128), 256, SMEM_BYTES>>>(
        pXhi, pXlo, pWhhi, pWhlo, bout,
        out, nullptr, nullptr, NTOK, VOCAB, DMODEL);
    softmax_rows<<<NTOK, 256>>>(out);
}